// round 14
// baseline (speedup 1.0000x reference)
#include <cuda_runtime.h>

// out[n, p] = sum_f matrix[p, f] * nf_perm[n, f]
// nf_perm[n] = (F0, F3, F1, F2),  F = field[batch[n]]
//
// R13 = confirmed-best R6 skeleton (47.1us timed x3, 52us ncu-locked) with
// ONE delta: output stores use st.global.wt (write-through) instead of
// __stcs. The 256 MB output stream is never re-read; write-through avoids
// L2 allocation + dirty-writeback scheduling for it entirely, while the
// field-table gathers keep their L2 residency. If the measured plateau has
// any L2-writeback component, this recovers it; sector-level write
// coalescing of the 512B-contiguous warp stores is unaffected.
//
// Skeleton (unchanged): 8 lanes per node, quad = lane&7 owns output floats
// [4q,4q+4) as one float4; persistent exactly-one-wave grid (148x6 blocks,
// regs<=42); quad loop-invariant -> matrix rows register-resident;
// batch-index software prefetch; positions input is dead.

__device__ __forceinline__ void stwt128(float4* addr, float4 v) {
    asm volatile("st.global.wt.v4.f32 [%0], {%1, %2, %3, %4};"
                 :: "l"(addr), "f"(v.x), "f"(v.y), "f"(v.z), "f"(v.w)
                 : "memory");
}

__global__ __launch_bounds__(256, 6) void dgto_kernel(
    const int*    __restrict__ batch,
    const float4* __restrict__ field,   // [n_graphs] rows of 4 floats
    const float4* __restrict__ matrix,  // 32 rows of 4 floats
    float4*       __restrict__ out,     // [n_nodes * 8] float4
    int total)                          // n_nodes * 8
{
    const int stride = gridDim.x * blockDim.x;   // multiple of 8
    int p = blockIdx.x * blockDim.x + threadIdx.x;

    const int quad = p & 7;  // loop-invariant
    const float4 m0 = __ldg(&matrix[quad * 4 + 0]);
    const float4 m1 = __ldg(&matrix[quad * 4 + 1]);
    const float4 m2 = __ldg(&matrix[quad * 4 + 2]);
    const float4 m3 = __ldg(&matrix[quad * 4 + 3]);

    // Prologue: indices for the first pair.
    int b0 = 0, b1 = 0;
    if (p < total)          b0 = __ldg(&batch[p >> 3]);
    if (p + stride < total) b1 = __ldg(&batch[(p + stride) >> 3]);

    while (p + stride < total) {
        // Field gathers for the current pair (indices prefetched last iter).
        const float4 f0 = __ldg(&field[b0]);
        const float4 f1 = __ldg(&field[b1]);

        // Prefetch next pair's indices while f0/f1 are in flight.
        const int pn = p + 2 * stride;
        int nb0 = 0, nb1 = 0;
        if (pn < total)          nb0 = __ldg(&batch[pn >> 3]);
        if (pn + stride < total) nb1 = __ldg(&batch[(pn + stride) >> 3]);

        // permuted node field: (x, w, y, z)
        float4 r0, r1;
        r0.x = m0.x * f0.x + m0.y * f0.w + m0.z * f0.y + m0.w * f0.z;
        r0.y = m1.x * f0.x + m1.y * f0.w + m1.z * f0.y + m1.w * f0.z;
        r0.z = m2.x * f0.x + m2.y * f0.w + m2.z * f0.y + m2.w * f0.z;
        r0.w = m3.x * f0.x + m3.y * f0.w + m3.z * f0.y + m3.w * f0.z;

        r1.x = m0.x * f1.x + m0.y * f1.w + m0.z * f1.y + m0.w * f1.z;
        r1.y = m1.x * f1.x + m1.y * f1.w + m1.z * f1.y + m1.w * f1.z;
        r1.z = m2.x * f1.x + m2.y * f1.w + m2.z * f1.y + m2.w * f1.z;
        r1.w = m3.x * f1.x + m3.y * f1.w + m3.z * f1.y + m3.w * f1.z;

        stwt128(&out[p],          r0);   // write-through: no L2 allocation
        stwt128(&out[p + stride], r1);

        b0 = nb0; b1 = nb1;
        p  = pn;
    }

    // Tail: at most one element per thread.
    if (p < total) {
        const float4 f = __ldg(&field[b0]);
        float4 r;
        r.x = m0.x * f.x + m0.y * f.w + m0.z * f.y + m0.w * f.z;
        r.y = m1.x * f.x + m1.y * f.w + m1.z * f.y + m1.w * f.z;
        r.z = m2.x * f.x + m2.y * f.w + m2.z * f.y + m2.w * f.z;
        r.w = m3.x * f.x + m3.y * f.w + m3.z * f.y + m3.w * f.z;
        stwt128(&out[p], r);
    }
}

extern "C" void kernel_launch(void* const* d_in, const int* in_sizes, int n_in,
                              void* d_out, int out_size)
{
    const int*    batch  = (const int*)d_in[0];
    // d_in[1] = positions (unused by the reference output)
    const float4* field  = (const float4*)d_in[2];
    const float4* matrix = (const float4*)d_in[3];
    float4*       out    = (float4*)d_out;

    const int n_nodes = in_sizes[0];
    const int total   = n_nodes * 8;   // float4 outputs

    // Exactly one resident wave: 6 blocks/SM (regs<=42) x 148 SMs.
    // Stride is a multiple of 8 so quad is loop-invariant per thread.
    const int block = 256;
    const int grid  = 148 * 6;

    dgto_kernel<<<grid, block>>>(batch, field, matrix, out, total);
}

// round 16
// speedup vs baseline: 1.2316x; 1.2316x over previous
#include <cuda_runtime.h>

// out[n, p] = sum_f matrix[p, f] * nf_perm[n, f]
// nf_perm[n] = (F0, F3, F1, F2),  F = field[batch[n]]
//
// FINAL — R6 structure, confirmed 47.136us timed on three independent runs
// (52.0-52.5us ncu-locked; best locked duration of all 12 variants tested).
//  - 8 lanes per node; quad = lane&7 owns output floats [4q,4q+4) as one
//    float4 -> each warp's STG.128s cover 512 contiguous, 512B-aligned bytes
//    (full-line writes, no read-for-ownership).
//  - Persistent exactly-one-wave grid (148 SMs x 6 blocks, regs=40<=42);
//    stride multiple of 8 keeps quad loop-invariant, so the 4 matrix rows
//    live in registers (zero shared-crossbar traffic in the loop).
//  - Batch-index software prefetch hides index->gather serialization.
//  - __stcs streaming stores (best of stcs/plain/write-through, measured).
//  - positions input is dead (reference discards the einsum using it).
// Measured-neutral: occupancy 73->95%, field-value double-buffering, unroll
// depth, sparse-select math, store cache policy, scalar gathers. Kernel is
// pinned at the DRAM write-stream plateau (~70% of 8TB/s spec on 264MB of
// compulsory traffic); no SM-side pipe exceeds 68%.

__global__ __launch_bounds__(256, 6) void dgto_kernel(
    const int*    __restrict__ batch,
    const float4* __restrict__ field,   // [n_graphs] rows of 4 floats
    const float4* __restrict__ matrix,  // 32 rows of 4 floats
    float4*       __restrict__ out,     // [n_nodes * 8] float4
    int total)                          // n_nodes * 8
{
    const int stride = gridDim.x * blockDim.x;   // multiple of 8
    int p = blockIdx.x * blockDim.x + threadIdx.x;

    const int quad = p & 7;  // loop-invariant
    const float4 m0 = __ldg(&matrix[quad * 4 + 0]);
    const float4 m1 = __ldg(&matrix[quad * 4 + 1]);
    const float4 m2 = __ldg(&matrix[quad * 4 + 2]);
    const float4 m3 = __ldg(&matrix[quad * 4 + 3]);

    // Prologue: indices for the first pair.
    int b0 = 0, b1 = 0;
    if (p < total)          b0 = __ldg(&batch[p >> 3]);
    if (p + stride < total) b1 = __ldg(&batch[(p + stride) >> 3]);

    while (p + stride < total) {
        // Field gathers for the current pair (indices prefetched last iter).
        const float4 f0 = __ldg(&field[b0]);
        const float4 f1 = __ldg(&field[b1]);

        // Prefetch next pair's indices while f0/f1 are in flight.
        const int pn = p + 2 * stride;
        int nb0 = 0, nb1 = 0;
        if (pn < total)          nb0 = __ldg(&batch[pn >> 3]);
        if (pn + stride < total) nb1 = __ldg(&batch[(pn + stride) >> 3]);

        // permuted node field: (x, w, y, z)
        float4 r0, r1;
        r0.x = m0.x * f0.x + m0.y * f0.w + m0.z * f0.y + m0.w * f0.z;
        r0.y = m1.x * f0.x + m1.y * f0.w + m1.z * f0.y + m1.w * f0.z;
        r0.z = m2.x * f0.x + m2.y * f0.w + m2.z * f0.y + m2.w * f0.z;
        r0.w = m3.x * f0.x + m3.y * f0.w + m3.z * f0.y + m3.w * f0.z;

        r1.x = m0.x * f1.x + m0.y * f1.w + m0.z * f1.y + m0.w * f1.z;
        r1.y = m1.x * f1.x + m1.y * f1.w + m1.z * f1.y + m1.w * f1.z;
        r1.z = m2.x * f1.x + m2.y * f1.w + m2.z * f1.y + m2.w * f1.z;
        r1.w = m3.x * f1.x + m3.y * f1.w + m3.z * f1.y + m3.w * f1.z;

        __stcs(&out[p],          r0);
        __stcs(&out[p + stride], r1);

        b0 = nb0; b1 = nb1;
        p  = pn;
    }

    // Tail: at most one element per thread.
    if (p < total) {
        const float4 f = __ldg(&field[b0]);
        float4 r;
        r.x = m0.x * f.x + m0.y * f.w + m0.z * f.y + m0.w * f.z;
        r.y = m1.x * f.x + m1.y * f.w + m1.z * f.y + m1.w * f.z;
        r.z = m2.x * f.x + m2.y * f.w + m2.z * f.y + m2.w * f.z;
        r.w = m3.x * f.x + m3.y * f.w + m3.z * f.y + m3.w * f.z;
        __stcs(&out[p], r);
    }
}

extern "C" void kernel_launch(void* const* d_in, const int* in_sizes, int n_in,
                              void* d_out, int out_size)
{
    const int*    batch  = (const int*)d_in[0];
    // d_in[1] = positions (unused by the reference output)
    const float4* field  = (const float4*)d_in[2];
    const float4* matrix = (const float4*)d_in[3];
    float4*       out    = (float4*)d_out;

    const int n_nodes = in_sizes[0];
    const int total   = n_nodes * 8;   // float4 outputs

    // Exactly one resident wave: 6 blocks/SM (regs<=42) x 148 SMs.
    // Stride is a multiple of 8 so quad is loop-invariant per thread.
    const int block = 256;
    const int grid  = 148 * 6;

    dgto_kernel<<<grid, block>>>(batch, field, matrix, out, total);
}